// round 2
// baseline (speedup 1.0000x reference)
#include <cuda_runtime.h>
#include <cstdint>

// Scratch for the intermediate xw = X @ W  ([N, 128] fp32, N = 100000)
// 100000 * 128 * 4 B = 51.2 MB — static device global (allocation-free).
__device__ float g_xw[100000 * 128];

// ---------------------------------------------------------------------------
// Pass 1: xw[x_rows[i], :] += x_vals[i] * W[x_cols[i], :]
// One warp per nonzero. Lane l handles output floats [4l, 4l+4).
// ---------------------------------------------------------------------------
__global__ void __launch_bounds__(256) xw_scatter_kernel(
    const float* __restrict__ x_vals,
    const int*   __restrict__ x_rows,
    const int*   __restrict__ x_cols,
    const float* __restrict__ W,     // [512, 128] row-major
    int nnz)
{
    int warp = (blockIdx.x * blockDim.x + threadIdx.x) >> 5;
    int lane = threadIdx.x & 31;
    if (warp >= nnz) return;

    int   row = x_rows[warp];
    int   col = x_cols[warp];
    float v   = x_vals[warp];

    // W row is 128 floats = 32 float4; lane l reads float4 #l (coalesced 512B).
    float4 w = reinterpret_cast<const float4*>(W)[col * 32 + lane];
    float4 r;
    r.x = w.x * v; r.y = w.y * v; r.z = w.z * v; r.w = w.w * v;

    float* dst = g_xw + (size_t)row * 128 + lane * 4;
    asm volatile("red.global.add.v4.f32 [%0], {%1, %2, %3, %4};"
                 :: "l"(dst), "f"(r.x), "f"(r.y), "f"(r.z), "f"(r.w)
                 : "memory");
}

// ---------------------------------------------------------------------------
// Pass 2: out[adj_rows[e], :] += adj_vals[e] * xw[adj_cols[e], :]
// One warp per edge. Gather 512B row of xw (L2-resident), scale, RED.128 out.
// ---------------------------------------------------------------------------
__global__ void __launch_bounds__(256) agg_scatter_kernel(
    const float* __restrict__ adj_vals,
    const int*   __restrict__ adj_rows,
    const int*   __restrict__ adj_cols,
    float*       __restrict__ out,   // [N, 128]
    int n_edges)
{
    int warp = (blockIdx.x * blockDim.x + threadIdx.x) >> 5;
    int lane = threadIdx.x & 31;
    if (warp >= n_edges) return;

    int   dst_row = adj_rows[warp];
    int   src_row = adj_cols[warp];
    float v       = adj_vals[warp];

    const float4* src = reinterpret_cast<const float4*>(g_xw) + (size_t)src_row * 32 + lane;
    float4 h = *src;
    float4 r;
    r.x = h.x * v; r.y = h.y * v; r.z = h.z * v; r.w = h.w * v;

    float* dst = out + (size_t)dst_row * 128 + lane * 4;
    asm volatile("red.global.add.v4.f32 [%0], {%1, %2, %3, %4};"
                 :: "l"(dst), "f"(r.x), "f"(r.y), "f"(r.z), "f"(r.w)
                 : "memory");
}

// ---------------------------------------------------------------------------
// Pass 3: out = relu(out), vectorized float4.
// ---------------------------------------------------------------------------
__global__ void __launch_bounds__(256) relu_kernel(float4* __restrict__ out, int n4)
{
    int i = blockIdx.x * blockDim.x + threadIdx.x;
    if (i >= n4) return;
    float4 v = out[i];
    v.x = v.x > 0.f ? v.x : 0.f;
    v.y = v.y > 0.f ? v.y : 0.f;
    v.z = v.z > 0.f ? v.z : 0.f;
    v.w = v.w > 0.f ? v.w : 0.f;
    out[i] = v;
}

extern "C" void kernel_launch(void* const* d_in, const int* in_sizes, int n_in,
                              void* d_out, int out_size)
{
    const float* x_vals   = (const float*)d_in[0];
    const int*   x_rows   = (const int*)  d_in[1];
    const int*   x_cols   = (const int*)  d_in[2];
    const float* adj_vals = (const float*)d_in[3];
    const int*   adj_rows = (const int*)  d_in[4];
    const int*   adj_cols = (const int*)  d_in[5];
    const float* W        = (const float*)d_in[6];
    // d_in[7] = n_nodes (scalar) — derive N from out_size instead (no sync read).

    int nnz_x   = in_sizes[0];
    int n_edges = in_sizes[3];
    int N       = out_size / 128;

    float* xw_ptr = nullptr;
    cudaGetSymbolAddress((void**)&xw_ptr, g_xw);

    // Zero the accumulators (memset nodes are graph-capturable).
    cudaMemsetAsync(xw_ptr, 0, (size_t)N * 128 * sizeof(float));
    cudaMemsetAsync(d_out, 0, (size_t)out_size * sizeof(float));

    // Pass 1: xw = X @ W (scatter)
    {
        long long threads = (long long)nnz_x * 32;
        int blocks = (int)((threads + 255) / 256);
        xw_scatter_kernel<<<blocks, 256>>>(x_vals, x_rows, x_cols, W, nnz_x);
    }

    // Pass 2: out = A @ xw (scatter)
    {
        long long threads = (long long)n_edges * 32;
        int blocks = (int)((threads + 255) / 256);
        agg_scatter_kernel<<<blocks, 256>>>(adj_vals, adj_rows, adj_cols,
                                            (float*)d_out, n_edges);
    }

    // Pass 3: relu in place
    {
        int n4 = out_size / 4;
        int blocks = (n4 + 255) / 256;
        relu_kernel<<<blocks, 256>>>((float4*)d_out, n4);
    }
}

// round 3
// speedup vs baseline: 1.9199x; 1.9199x over previous
#include <cuda_runtime.h>
#include <cstdint>

#define MAXN   100000
#define MAXNNZ 800000
#define MAXNE  1600000
#define SCAN_B 1024

// Scratch (static device globals — allocation-free).
__device__ float  g_xw[(size_t)MAXN * 128];          // intermediate X@W  [N,128]
__device__ int    g_cnt_x[MAXN], g_cur_x[MAXN], g_row_x[MAXN + 1];
__device__ int    g_cnt_a[MAXN], g_cur_a[MAXN], g_row_a[MAXN + 1];
__device__ int    g_bsum_x[128], g_bsum_a[128];      // block sums for scans
__device__ float2 g_px[MAXNNZ];                      // permuted X nnz: (val, bitcast col)
__device__ float2 g_pa[MAXNE];                       // permuted A nnz: (val, bitcast src)

// ---------------------------------------------------------------------------
// Histogram: cnt[rows[i]]++
// ---------------------------------------------------------------------------
__global__ void __launch_bounds__(256) hist_kernel(const int* __restrict__ rows,
                                                   int n, int* __restrict__ cnt)
{
    int i = blockIdx.x * blockDim.x + threadIdx.x;
    if (i < n) atomicAdd(&cnt[rows[i]], 1);
}

// ---------------------------------------------------------------------------
// Scan stage 1: per-block (1024) inclusive scan + block sums.
// ---------------------------------------------------------------------------
__global__ void __launch_bounds__(SCAN_B) scan_block_kernel(
    const int* __restrict__ cnt, int* __restrict__ incl,
    int* __restrict__ bsum, int n)
{
    __shared__ int sh[SCAN_B];
    int gid = blockIdx.x * SCAN_B + threadIdx.x;
    int v = (gid < n) ? cnt[gid] : 0;
    sh[threadIdx.x] = v;
    __syncthreads();
#pragma unroll
    for (int off = 1; off < SCAN_B; off <<= 1) {
        int t = (threadIdx.x >= off) ? sh[threadIdx.x - off] : 0;
        __syncthreads();
        sh[threadIdx.x] += t;
        __syncthreads();
    }
    if (gid < n) incl[gid] = sh[threadIdx.x];
    if (threadIdx.x == SCAN_B - 1) bsum[blockIdx.x] = sh[SCAN_B - 1];
}

// ---------------------------------------------------------------------------
// Scan stage 2: exclusive scan of block sums (single block, nb <= 1024).
// ---------------------------------------------------------------------------
__global__ void __launch_bounds__(SCAN_B) scan_sums_kernel(int* __restrict__ bsum, int nb)
{
    __shared__ int sh[SCAN_B];
    int v = (threadIdx.x < nb) ? bsum[threadIdx.x] : 0;
    sh[threadIdx.x] = v;
    __syncthreads();
#pragma unroll
    for (int off = 1; off < SCAN_B; off <<= 1) {
        int t = (threadIdx.x >= off) ? sh[threadIdx.x - off] : 0;
        __syncthreads();
        sh[threadIdx.x] += t;
        __syncthreads();
    }
    if (threadIdx.x < nb) bsum[threadIdx.x] = sh[threadIdx.x] - v;  // exclusive
}

// ---------------------------------------------------------------------------
// Scan stage 3: row_start[i] = incl[i] + bsum[block] - cnt[i]; row_start[n] = total.
// (incl[] aliases a temp; we reuse cur[] as the incl buffer, then re-zero it.)
// ---------------------------------------------------------------------------
__global__ void __launch_bounds__(256) finalize_kernel(
    const int* __restrict__ incl, const int* __restrict__ bsum,
    const int* __restrict__ cnt, int* __restrict__ row_start, int n)
{
    int gid = blockIdx.x * blockDim.x + threadIdx.x;
    if (gid >= n) return;
    int e = incl[gid] + bsum[gid >> 10];
    row_start[gid] = e - cnt[gid];
    if (gid == n - 1) row_start[n] = e;
}

// ---------------------------------------------------------------------------
// Permutation scatter: bucket (val, col) pairs by row.
// ---------------------------------------------------------------------------
__global__ void __launch_bounds__(256) scatter_kernel(
    const float* __restrict__ vals, const int* __restrict__ rows,
    const int* __restrict__ cols, const int* __restrict__ row_start,
    int* __restrict__ cur, float2* __restrict__ perm, int n)
{
    int i = blockIdx.x * blockDim.x + threadIdx.x;
    if (i >= n) return;
    int r   = rows[i];
    int pos = row_start[r] + atomicAdd(&cur[r], 1);
    perm[pos] = make_float2(vals[i], __int_as_float(cols[i]));
}

// ---------------------------------------------------------------------------
// Pass 1 (CSR): xw[r,:] = sum_j val_j * W[col_j,:].  One warp per row,
// lane l owns floats [4l,4l+4). W is 256 KB -> L1/L2 resident. Single store.
// ---------------------------------------------------------------------------
__global__ void __launch_bounds__(256) spmm_xw_kernel(
    const int* __restrict__ row_start, const float2* __restrict__ perm,
    const float* __restrict__ W, int N)
{
    int warp = (blockIdx.x * blockDim.x + threadIdx.x) >> 5;
    int lane = threadIdx.x & 31;
    if (warp >= N) return;
    int s = row_start[warp], e = row_start[warp + 1];

    float4 acc = make_float4(0.f, 0.f, 0.f, 0.f);
    int j = s;
    for (; j + 1 < e; j += 2) {
        float2 p0 = perm[j], p1 = perm[j + 1];
        float4 w0 = __ldg((const float4*)W + (size_t)__float_as_int(p0.y) * 32 + lane);
        float4 w1 = __ldg((const float4*)W + (size_t)__float_as_int(p1.y) * 32 + lane);
        acc.x = fmaf(p0.x, w0.x, acc.x); acc.y = fmaf(p0.x, w0.y, acc.y);
        acc.z = fmaf(p0.x, w0.z, acc.z); acc.w = fmaf(p0.x, w0.w, acc.w);
        acc.x = fmaf(p1.x, w1.x, acc.x); acc.y = fmaf(p1.x, w1.y, acc.y);
        acc.z = fmaf(p1.x, w1.z, acc.z); acc.w = fmaf(p1.x, w1.w, acc.w);
    }
    if (j < e) {
        float2 p = perm[j];
        float4 w = __ldg((const float4*)W + (size_t)__float_as_int(p.y) * 32 + lane);
        acc.x = fmaf(p.x, w.x, acc.x); acc.y = fmaf(p.x, w.y, acc.y);
        acc.z = fmaf(p.x, w.z, acc.z); acc.w = fmaf(p.x, w.w, acc.w);
    }
    reinterpret_cast<float4*>(g_xw)[(size_t)warp * 32 + lane] = acc;
}

// ---------------------------------------------------------------------------
// Pass 2 (CSR): out[r,:] = relu( sum_e val_e * xw[src_e,:] ). One warp per
// dst row; gathers are 512B coalesced rows from L2-resident xw. Single store.
// ---------------------------------------------------------------------------
__global__ void __launch_bounds__(256) spmm_agg_kernel(
    const int* __restrict__ row_start, const float2* __restrict__ perm,
    float* __restrict__ out, int N)
{
    int warp = (blockIdx.x * blockDim.x + threadIdx.x) >> 5;
    int lane = threadIdx.x & 31;
    if (warp >= N) return;
    int s = row_start[warp], e = row_start[warp + 1];

    const float4* xw4 = reinterpret_cast<const float4*>(g_xw);
    float4 acc = make_float4(0.f, 0.f, 0.f, 0.f);
    int j = s;
    for (; j + 1 < e; j += 2) {
        float2 p0 = perm[j], p1 = perm[j + 1];
        float4 h0 = __ldg(xw4 + (size_t)__float_as_int(p0.y) * 32 + lane);
        float4 h1 = __ldg(xw4 + (size_t)__float_as_int(p1.y) * 32 + lane);
        acc.x = fmaf(p0.x, h0.x, acc.x); acc.y = fmaf(p0.x, h0.y, acc.y);
        acc.z = fmaf(p0.x, h0.z, acc.z); acc.w = fmaf(p0.x, h0.w, acc.w);
        acc.x = fmaf(p1.x, h1.x, acc.x); acc.y = fmaf(p1.x, h1.y, acc.y);
        acc.z = fmaf(p1.x, h1.z, acc.z); acc.w = fmaf(p1.x, h1.w, acc.w);
    }
    if (j < e) {
        float2 p = perm[j];
        float4 h = __ldg(xw4 + (size_t)__float_as_int(p.y) * 32 + lane);
        acc.x = fmaf(p.x, h.x, acc.x); acc.y = fmaf(p.x, h.y, acc.y);
        acc.z = fmaf(p.x, h.z, acc.z); acc.w = fmaf(p.x, h.w, acc.w);
    }
    // fused relu
    acc.x = acc.x > 0.f ? acc.x : 0.f;
    acc.y = acc.y > 0.f ? acc.y : 0.f;
    acc.z = acc.z > 0.f ? acc.z : 0.f;
    acc.w = acc.w > 0.f ? acc.w : 0.f;
    reinterpret_cast<float4*>(out)[(size_t)warp * 32 + lane] = acc;
}

// ---------------------------------------------------------------------------
extern "C" void kernel_launch(void* const* d_in, const int* in_sizes, int n_in,
                              void* d_out, int out_size)
{
    const float* x_vals   = (const float*)d_in[0];
    const int*   x_rows   = (const int*)  d_in[1];
    const int*   x_cols   = (const int*)  d_in[2];
    const float* adj_vals = (const float*)d_in[3];
    const int*   adj_rows = (const int*)  d_in[4];
    const int*   adj_cols = (const int*)  d_in[5];
    const float* W        = (const float*)d_in[6];

    int nnz_x   = in_sizes[0];
    int n_edges = in_sizes[3];
    int N       = out_size / 128;

    int *cnt_x, *cur_x, *row_x, *bsum_x;
    int *cnt_a, *cur_a, *row_a, *bsum_a;
    float2 *px, *pa;
    cudaGetSymbolAddress((void**)&cnt_x,  g_cnt_x);
    cudaGetSymbolAddress((void**)&cur_x,  g_cur_x);
    cudaGetSymbolAddress((void**)&row_x,  g_row_x);
    cudaGetSymbolAddress((void**)&bsum_x, g_bsum_x);
    cudaGetSymbolAddress((void**)&cnt_a,  g_cnt_a);
    cudaGetSymbolAddress((void**)&cur_a,  g_cur_a);
    cudaGetSymbolAddress((void**)&row_a,  g_row_a);
    cudaGetSymbolAddress((void**)&bsum_a, g_bsum_a);
    cudaGetSymbolAddress((void**)&px,     g_px);
    cudaGetSymbolAddress((void**)&pa,     g_pa);

    const int T = 256;
    int nb_scan = (N + SCAN_B - 1) / SCAN_B;

    // Zero counters + cursors (tiny memsets, graph-capturable).
    cudaMemsetAsync(cnt_x, 0, N * sizeof(int));
    cudaMemsetAsync(cnt_a, 0, N * sizeof(int));
    cudaMemsetAsync(cur_x, 0, N * sizeof(int));
    cudaMemsetAsync(cur_a, 0, N * sizeof(int));

    // Histograms by destination row.
    hist_kernel<<<(nnz_x   + T - 1) / T, T>>>(x_rows,   nnz_x,   cnt_x);
    hist_kernel<<<(n_edges + T - 1) / T, T>>>(adj_rows, n_edges, cnt_a);

    // Scans -> row_start arrays. (Use cur_* as the temp inclusive buffer,
    // then re-zero it before the permutation scatter.)
    scan_block_kernel<<<nb_scan, SCAN_B>>>(cnt_x, cur_x, bsum_x, N);
    scan_block_kernel<<<nb_scan, SCAN_B>>>(cnt_a, cur_a, bsum_a, N);
    scan_sums_kernel<<<1, SCAN_B>>>(bsum_x, nb_scan);
    scan_sums_kernel<<<1, SCAN_B>>>(bsum_a, nb_scan);
    finalize_kernel<<<(N + T - 1) / T, T>>>(cur_x, bsum_x, cnt_x, row_x, N);
    finalize_kernel<<<(N + T - 1) / T, T>>>(cur_a, bsum_a, cnt_a, row_a, N);
    cudaMemsetAsync(cur_x, 0, N * sizeof(int));
    cudaMemsetAsync(cur_a, 0, N * sizeof(int));

    // Bucket the nonzeros by destination row.
    scatter_kernel<<<(nnz_x   + T - 1) / T, T>>>(x_vals,   x_rows,   x_cols,
                                                 row_x, cur_x, px, nnz_x);
    scatter_kernel<<<(n_edges + T - 1) / T, T>>>(adj_vals, adj_rows, adj_cols,
                                                 row_a, cur_a, pa, n_edges);

    // Pass 1: xw = X @ W  (atomic-free, one warp per row)
    {
        int blocks = (N * 32 + T - 1) / T;
        spmm_xw_kernel<<<blocks, T>>>(row_x, px, W, N);
    }
    // Pass 2: out = relu(A @ xw)  (atomic-free, relu fused)
    {
        int blocks = (N * 32 + T - 1) / T;
        spmm_agg_kernel<<<blocks, T>>>(row_a, pa, (float*)d_out, N);
    }
}

// round 5
// speedup vs baseline: 2.4459x; 1.2740x over previous
#include <cuda_runtime.h>
#include <cuda_fp16.h>
#include <cstdint>

#define MAXN   100000
#define MAXNNZ 800000
#define MAXNE  1600000
#define SCAN_B 1024

// ---------------------------------------------------------------------------
// Scratch (static device globals — allocation-free).
// g_xw stored in fp16: halves pass-2 gather traffic (L2-bound).
// ---------------------------------------------------------------------------
__device__ __half  g_xw[(size_t)MAXN * 128];

__device__ int g_cnt[2 * MAXN];
__device__ int g_cur[2 * MAXN];
__device__ int g_row[2 * MAXN + 2];
__device__ int g_bsum[256];

__device__ float2 g_px[MAXNNZ];   // permuted X nnz: (val, bitcast col)
__device__ float2 g_pa[MAXNE];    // permuted A nnz: (val, bitcast src)

// ---------------------------------------------------------------------------
// Combined histogram: i < nnz_x -> cnt[x_rows[i]]++, else cnt[N + adj_rows[..]]++
// ---------------------------------------------------------------------------
__global__ void __launch_bounds__(256) hist2_kernel(
    const int* __restrict__ x_rows, int nnz_x,
    const int* __restrict__ adj_rows, int n_edges,
    int* __restrict__ cnt, int N)
{
    int i = blockIdx.x * blockDim.x + threadIdx.x;
    if (i < nnz_x) {
        atomicAdd(&cnt[x_rows[i]], 1);
    } else if (i < nnz_x + n_edges) {
        atomicAdd(&cnt[N + adj_rows[i - nnz_x]], 1);
    }
}

// ---------------------------------------------------------------------------
// Scan stage 1: per-block (1024) inclusive scan + block sums over cnt[0..2N).
// ---------------------------------------------------------------------------
__global__ void __launch_bounds__(SCAN_B) scan_block_kernel(
    const int* __restrict__ cnt, int* __restrict__ incl,
    int* __restrict__ bsum, int n)
{
    __shared__ int sh[SCAN_B];
    int gid = blockIdx.x * SCAN_B + threadIdx.x;
    int v = (gid < n) ? cnt[gid] : 0;
    sh[threadIdx.x] = v;
    __syncthreads();
#pragma unroll
    for (int off = 1; off < SCAN_B; off <<= 1) {
        int t = (threadIdx.x >= off) ? sh[threadIdx.x - off] : 0;
        __syncthreads();
        sh[threadIdx.x] += t;
        __syncthreads();
    }
    if (gid < n) incl[gid] = sh[threadIdx.x];
    if (threadIdx.x == SCAN_B - 1) bsum[blockIdx.x] = sh[SCAN_B - 1];
}

// ---------------------------------------------------------------------------
// Scan stage 2: exclusive scan of block sums (single block, nb <= 1024).
// ---------------------------------------------------------------------------
__global__ void __launch_bounds__(SCAN_B) scan_sums_kernel(int* __restrict__ bsum, int nb)
{
    __shared__ int sh[SCAN_B];
    int v = (threadIdx.x < nb) ? bsum[threadIdx.x] : 0;
    sh[threadIdx.x] = v;
    __syncthreads();
#pragma unroll
    for (int off = 1; off < SCAN_B; off <<= 1) {
        int t = (threadIdx.x >= off) ? sh[threadIdx.x - off] : 0;
        __syncthreads();
        sh[threadIdx.x] += t;
        __syncthreads();
    }
    if (threadIdx.x < nb) bsum[threadIdx.x] = sh[threadIdx.x] - v;  // exclusive
}

// ---------------------------------------------------------------------------
// Scan stage 3: row_start = incl + bsum[blk] - cnt. Writes BOTH row[] and
// cur[] (cursor init = row_start, so scatter needs no re-zero memset).
// ---------------------------------------------------------------------------
__global__ void __launch_bounds__(256) finalize_kernel(
    const int* __restrict__ incl, const int* __restrict__ bsum,
    const int* __restrict__ cnt, int* __restrict__ row_start,
    int* __restrict__ cur, int n)
{
    int gid = blockIdx.x * blockDim.x + threadIdx.x;
    if (gid >= n) return;
    int e = incl[gid] + bsum[gid >> 10];
    int st = e - cnt[gid];
    row_start[gid] = st;
    cur[gid]       = st;
    if (gid == n - 1) row_start[n] = e;
}

// ---------------------------------------------------------------------------
// Combined permutation scatter. cur[] pre-initialized to row_start.
// A-side write positions rebased by -nnz_x (A rows occupy cnt[N..2N) whose
// global offsets start at nnz_x).
// ---------------------------------------------------------------------------
__global__ void __launch_bounds__(256) scatter2_kernel(
    const float* __restrict__ x_vals, const int* __restrict__ x_rows,
    const int* __restrict__ x_cols, int nnz_x,
    const float* __restrict__ adj_vals, const int* __restrict__ adj_rows,
    const int* __restrict__ adj_cols, int n_edges,
    int* __restrict__ cur, float2* __restrict__ px, float2* __restrict__ pa,
    int N)
{
    int i = blockIdx.x * blockDim.x + threadIdx.x;
    if (i < nnz_x) {
        int r   = x_rows[i];
        int pos = atomicAdd(&cur[r], 1);
        px[pos] = make_float2(x_vals[i], __int_as_float(x_cols[i]));
    } else if (i < nnz_x + n_edges) {
        int k   = i - nnz_x;
        int r   = adj_rows[k];
        int pos = atomicAdd(&cur[N + r], 1) - nnz_x;
        pa[pos] = make_float2(adj_vals[k], __int_as_float(adj_cols[k]));
    }
}

// ---------------------------------------------------------------------------
// Pass 1 (CSR): xw[r,:] = sum_j val_j * W[col_j,:], stored fp16.
// One warp per row; lane l owns floats [4l,4l+4). Single 8B store per lane.
// ---------------------------------------------------------------------------
__global__ void __launch_bounds__(256) spmm_xw_kernel(
    const int* __restrict__ row_start, const float2* __restrict__ perm,
    const float* __restrict__ W, int N)
{
    int warp = (blockIdx.x * blockDim.x + threadIdx.x) >> 5;
    int lane = threadIdx.x & 31;
    if (warp >= N) return;
    int s = row_start[warp], e = row_start[warp + 1];

    float4 acc = make_float4(0.f, 0.f, 0.f, 0.f);
    int j = s;
    for (; j + 1 < e; j += 2) {
        float2 p0 = perm[j], p1 = perm[j + 1];
        float4 w0 = __ldg((const float4*)W + (size_t)__float_as_int(p0.y) * 32 + lane);
        float4 w1 = __ldg((const float4*)W + (size_t)__float_as_int(p1.y) * 32 + lane);
        acc.x = fmaf(p0.x, w0.x, acc.x); acc.y = fmaf(p0.x, w0.y, acc.y);
        acc.z = fmaf(p0.x, w0.z, acc.z); acc.w = fmaf(p0.x, w0.w, acc.w);
        acc.x = fmaf(p1.x, w1.x, acc.x); acc.y = fmaf(p1.x, w1.y, acc.y);
        acc.z = fmaf(p1.x, w1.z, acc.z); acc.w = fmaf(p1.x, w1.w, acc.w);
    }
    if (j < e) {
        float2 p = perm[j];
        float4 w = __ldg((const float4*)W + (size_t)__float_as_int(p.y) * 32 + lane);
        acc.x = fmaf(p.x, w.x, acc.x); acc.y = fmaf(p.x, w.y, acc.y);
        acc.z = fmaf(p.x, w.z, acc.z); acc.w = fmaf(p.x, w.w, acc.w);
    }
    __half2 h01 = __floats2half2_rn(acc.x, acc.y);
    __half2 h23 = __floats2half2_rn(acc.z, acc.w);
    uint2 packed = make_uint2(*reinterpret_cast<uint32_t*>(&h01),
                              *reinterpret_cast<uint32_t*>(&h23));
    reinterpret_cast<uint2*>(g_xw)[(size_t)warp * 32 + lane] = packed;
}

// ---------------------------------------------------------------------------
// Pass 2 (CSR): out[r,:] = relu( sum_e val_e * xw_h[src_e,:] ).
// row_start entries carry a global base (nnz_x) — subtract it for pa indexing.
// ---------------------------------------------------------------------------
__device__ __forceinline__ void fma_row(float4& acc, float v, uint2 raw)
{
    __half2 h01 = *reinterpret_cast<__half2*>(&raw.x);
    __half2 h23 = *reinterpret_cast<__half2*>(&raw.y);
    float2 f01 = __half22float2(h01);
    float2 f23 = __half22float2(h23);
    acc.x = fmaf(v, f01.x, acc.x); acc.y = fmaf(v, f01.y, acc.y);
    acc.z = fmaf(v, f23.x, acc.z); acc.w = fmaf(v, f23.y, acc.w);
}

__global__ void __launch_bounds__(256) spmm_agg_kernel(
    const int* __restrict__ row_start, const float2* __restrict__ perm,
    float* __restrict__ out, int N, int base)
{
    int warp = (blockIdx.x * blockDim.x + threadIdx.x) >> 5;
    int lane = threadIdx.x & 31;
    if (warp >= N) return;
    int s = row_start[warp] - base, e = row_start[warp + 1] - base;

    const uint2* xw2 = reinterpret_cast<const uint2*>(g_xw);
    float4 acc = make_float4(0.f, 0.f, 0.f, 0.f);
    int j = s;
    for (; j + 3 < e; j += 4) {
        float2 p0 = perm[j],     p1 = perm[j + 1];
        float2 p2 = perm[j + 2], p3 = perm[j + 3];
        uint2 r0 = __ldg(xw2 + (size_t)__float_as_int(p0.y) * 32 + lane);
        uint2 r1 = __ldg(xw2 + (size_t)__float_as_int(p1.y) * 32 + lane);
        uint2 r2 = __ldg(xw2 + (size_t)__float_as_int(p2.y) * 32 + lane);
        uint2 r3 = __ldg(xw2 + (size_t)__float_as_int(p3.y) * 32 + lane);
        fma_row(acc, p0.x, r0);
        fma_row(acc, p1.x, r1);
        fma_row(acc, p2.x, r2);
        fma_row(acc, p3.x, r3);
    }
    for (; j < e; ++j) {
        float2 p = perm[j];
        uint2 r = __ldg(xw2 + (size_t)__float_as_int(p.y) * 32 + lane);
        fma_row(acc, p.x, r);
    }
    acc.x = acc.x > 0.f ? acc.x : 0.f;
    acc.y = acc.y > 0.f ? acc.y : 0.f;
    acc.z = acc.z > 0.f ? acc.z : 0.f;
    acc.w = acc.w > 0.f ? acc.w : 0.f;
    reinterpret_cast<float4*>(out)[(size_t)warp * 32 + lane] = acc;
}

// ---------------------------------------------------------------------------
extern "C" void kernel_launch(void* const* d_in, const int* in_sizes, int n_in,
                              void* d_out, int out_size)
{
    const float* x_vals   = (const float*)d_in[0];
    const int*   x_rows   = (const int*)  d_in[1];
    const int*   x_cols   = (const int*)  d_in[2];
    const float* adj_vals = (const float*)d_in[3];
    const int*   adj_rows = (const int*)  d_in[4];
    const int*   adj_cols = (const int*)  d_in[5];
    const float* W        = (const float*)d_in[6];

    int nnz_x   = in_sizes[0];
    int n_edges = in_sizes[3];
    int N       = out_size / 128;
    int n2      = 2 * N;

    int *cnt, *cur, *row, *bsum;
    float2 *px, *pa;
    cudaGetSymbolAddress((void**)&cnt,  g_cnt);
    cudaGetSymbolAddress((void**)&cur,  g_cur);
    cudaGetSymbolAddress((void**)&row,  g_row);
    cudaGetSymbolAddress((void**)&bsum, g_bsum);
    cudaGetSymbolAddress((void**)&px,   g_px);
    cudaGetSymbolAddress((void**)&pa,   g_pa);

    const int T = 256;
    int total   = nnz_x + n_edges;
    int nb_scan = (n2 + SCAN_B - 1) / SCAN_B;

    cudaMemsetAsync(cnt, 0, n2 * sizeof(int));

    hist2_kernel<<<(total + T - 1) / T, T>>>(x_rows, nnz_x, adj_rows, n_edges, cnt, N);

    scan_block_kernel<<<nb_scan, SCAN_B>>>(cnt, cur, bsum, n2);   // cur = temp incl
    scan_sums_kernel<<<1, SCAN_B>>>(bsum, nb_scan);
    finalize_kernel<<<(n2 + T - 1) / T, T>>>(cur, bsum, cnt, row, cur, n2);

    scatter2_kernel<<<(total + T - 1) / T, T>>>(
        x_vals, x_rows, x_cols, nnz_x,
        adj_vals, adj_rows, adj_cols, n_edges,
        cur, px, pa, N);

    // Pass 1: xw = X @ W (fp16 store, atomic-free).
    spmm_xw_kernel<<<(N * 32 + T - 1) / T, T>>>(row, px, W, N);

    // Pass 2: out = relu(A @ xw). A-side row offsets carry +nnz_x base.
    spmm_agg_kernel<<<(N * 32 + T - 1) / T, T>>>(row + N, pa, (float*)d_out, N, nnz_x);
}